// round 7
// baseline (speedup 1.0000x reference)
#include <cuda_runtime.h>

// CondFilterT: out[b,0:64] = table[input[b,0]];
// out[b,64+64c:+64] = v_c * (e_nrm . v_c)/(v_c . v_c),  v_c = table[input[b,1+c]]
// BATCH=16384, NCONDS=50, EMB=64.

#define BATCH   16384
#define NCONDS  50
#define ROW_IN  51
#define ROW_OUT 3264

__device__ __forceinline__ float dot4(float4 a, float4 b) {
    return fmaf(a.x, b.x, fmaf(a.y, b.y, fmaf(a.z, b.z, a.w * b.w)));
}
__device__ __forceinline__ float4 scale4(float4 a, float s) {
    return make_float4(a.x * s, a.y * s, a.z * s, a.w * s);
}

__global__ __launch_bounds__(128, 14)
void cond_filter_kernel(const int* __restrict__ inp,
                        const float* __restrict__ tab,
                        float* __restrict__ out)
{
    const int b   = blockIdx.x;
    const int tid = threadIdx.x;
    const int oct = tid >> 3;     // 0..15 (8-lane groups)
    const int ol  = tid & 7;      // lane in octet: covers dims [ol*8, ol*8+8)
    const int wid = tid >> 5;

    __shared__ int s_idx[ROW_IN];
    if (tid < ROW_IN)
        s_idx[tid] = inp[(size_t)b * ROW_IN + tid];
    __syncthreads();

    const float4* __restrict__ tab4 = reinterpret_cast<const float4*>(tab);
    float4* __restrict__ out4 = reinterpret_cast<float4*>(out + (size_t)b * ROW_OUT);

    // ---- Event embedding: every warp computes e_nrm (octet-sliced) ----
    float4 ena, enb;
    {
        const size_t eo = (size_t)s_idx[0] * 16 + ol * 2;
        const float4 ea = __ldg(&tab4[eo]);
        const float4 eb = __ldg(&tab4[eo + 1]);
        if (tid < 8) {                     // threads 0..7 write out[b,0:64] raw
            out4[2 * tid]     = ea;
            out4[2 * tid + 1] = eb;
        }
        float ss = dot4(ea, ea) + dot4(eb, eb);
        #pragma unroll
        for (int o = 4; o > 0; o >>= 1)
            ss += __shfl_xor_sync(0xffffffffu, ss, o);
        const float inv = rsqrtf(ss);
        ena = scale4(ea, inv);
        enb = scale4(eb, inv);
    }

    // reduce + scale + store one condition (all warp lanes hit the shuffles)
    #define PROC(va, vb, c, do_store)                                          \
    {                                                                          \
        float vv = dot4(va, va) + dot4(vb, vb);                                \
        float ev = dot4(ena, va) + dot4(enb, vb);                              \
        _Pragma("unroll")                                                      \
        for (int o = 4; o > 0; o >>= 1) {                                      \
            vv += __shfl_xor_sync(0xffffffffu, vv, o);                         \
            ev += __shfl_xor_sync(0xffffffffu, ev, o);                         \
        }                                                                      \
        if (do_store) {                                                        \
            const float s = __fdividef(ev, vv);                                \
            const size_t oo = 16 + (size_t)(c) * 16 + ol * 2;                  \
            out4[oo]     = scale4(va, s);                                      \
            out4[oo + 1] = scale4(vb, s);                                      \
        }                                                                      \
    }

    // ---- 3 rounds: octet o handles conds o, o+16, o+32 (software-pipelined) ----
    const int i0 = s_idx[1 + oct];
    const int i1 = s_idx[1 + oct + 16];
    const int i2 = s_idx[1 + oct + 32];

    const size_t lo = (size_t)ol * 2;
    float4 v0a = __ldg(&tab4[(size_t)i0 * 16 + lo]);
    float4 v0b = __ldg(&tab4[(size_t)i0 * 16 + lo + 1]);
    float4 v1a = __ldg(&tab4[(size_t)i1 * 16 + lo]);
    float4 v1b = __ldg(&tab4[(size_t)i1 * 16 + lo + 1]);

    PROC(v0a, v0b, oct, true);

    float4 v2a = __ldg(&tab4[(size_t)i2 * 16 + lo]);
    float4 v2b = __ldg(&tab4[(size_t)i2 * 16 + lo + 1]);

    PROC(v1a, v1b, oct + 16, true);
    PROC(v2a, v2b, oct + 32, true);

    // ---- Tail: conds 48 (octet 0, warp 0) and 49 (octet 8, warp 2).
    // Branch is warp-uniform, so the shuffles inside see a full warp.
    if (wid == 0 || wid == 2) {
        const bool mine = (oct == 0) || (oct == 8);
        const int c3 = 48 + (oct >> 3);                 // 48 or 49
        const int i3 = mine ? s_idx[1 + c3] : s_idx[1];  // dummy row if not mine
        float4 v3a = __ldg(&tab4[(size_t)i3 * 16 + lo]);
        float4 v3b = __ldg(&tab4[(size_t)i3 * 16 + lo + 1]);
        PROC(v3a, v3b, c3, mine);
    }
    #undef PROC
}

extern "C" void kernel_launch(void* const* d_in, const int* in_sizes, int n_in,
                              void* d_out, int out_size)
{
    const int*   inp = (const int*)d_in[0];
    const float* tab = (const float*)d_in[1];
    float*       out = (float*)d_out;
    (void)in_sizes; (void)n_in; (void)out_size;

    cond_filter_kernel<<<BATCH, 128>>>(inp, tab, out);
}

// round 8
// speedup vs baseline: 1.2089x; 1.2089x over previous
#include <cuda_runtime.h>

// CondFilterT: out[b,0:64] = table[input[b,0]];
// out[b,64+64c:+64] = v_c * (e_nrm . v_c)/(v_c . v_c),  v_c = table[input[b,1+c]]
// BATCH=16384, NCONDS=50, EMB=64.

#define BATCH   16384
#define NCONDS  50
#define ROW_IN  51
#define ROW_OUT 3264

__device__ __forceinline__ float dot4(float4 a, float4 b) {
    return fmaf(a.x, b.x, fmaf(a.y, b.y, fmaf(a.z, b.z, a.w * b.w)));
}
__device__ __forceinline__ float4 scale4(float4 a, float s) {
    return make_float4(a.x * s, a.y * s, a.z * s, a.w * s);
}

__global__ __launch_bounds__(128, 12)
void cond_filter_kernel(const int* __restrict__ inp,
                        const float* __restrict__ tab,
                        float* __restrict__ out)
{
    const int b   = blockIdx.x;
    const int tid = threadIdx.x;
    const int oct = tid >> 3;     // 0..15 (8-lane reduction groups)
    const int ol  = tid & 7;      // lane in octet
    const int wid = tid >> 5;

    __shared__ int s_idx[ROW_IN];
    if (tid < ROW_IN)
        s_idx[tid] = inp[(size_t)b * ROW_IN + tid];
    __syncthreads();

    const float4* __restrict__ tab4 = reinterpret_cast<const float4*>(tab);
    float4* __restrict__ out4 = reinterpret_cast<float4*>(out + (size_t)b * ROW_OUT);

    // Layout: lane ol owns float4 offsets {ol, ol+8} of each 16-float4 row.
    // => every warp LDG/STG instruction covers 4 x 128B CONTIGUOUS line runs.

    // ---- Event embedding: every warp computes e_nrm (octet-sliced) ----
    float4 ena, enb;
    {
        const size_t eo = (size_t)s_idx[0] * 16;
        const float4 ea = __ldg(&tab4[eo + ol]);
        const float4 eb = __ldg(&tab4[eo + ol + 8]);
        if (tid < 8) {                     // octet 0 writes out[b,0:64] raw
            out4[ol]     = ea;
            out4[ol + 8] = eb;
        }
        float ss = dot4(ea, ea) + dot4(eb, eb);
        #pragma unroll
        for (int o = 4; o > 0; o >>= 1)
            ss += __shfl_xor_sync(0xffffffffu, ss, o);
        const float inv = rsqrtf(ss);
        ena = scale4(ea, inv);
        enb = scale4(eb, inv);
    }

    // reduce + scale + store one condition (warp-wide shuffles, 4 conds/warp)
    #define PROC(va, vb, c, do_store)                                          \
    {                                                                          \
        float vv = dot4(va, va) + dot4(vb, vb);                                \
        float ev = dot4(ena, va) + dot4(enb, vb);                              \
        _Pragma("unroll")                                                      \
        for (int o = 4; o > 0; o >>= 1) {                                      \
            vv += __shfl_xor_sync(0xffffffffu, vv, o);                         \
            ev += __shfl_xor_sync(0xffffffffu, ev, o);                         \
        }                                                                      \
        if (do_store) {                                                        \
            const float s = __fdividef(ev, vv);                                \
            float4* __restrict__ dst = out4 + 16 + (size_t)(c) * 16;           \
            dst[ol]     = scale4(va, s);                                       \
            dst[ol + 8] = scale4(vb, s);                                       \
        }                                                                      \
    }

    // ---- Main: octet o handles conds o, o+16, o+32. All gathers front-batched. ----
    const size_t r0 = (size_t)s_idx[1 + oct]      * 16;
    const size_t r1 = (size_t)s_idx[1 + oct + 16] * 16;
    const size_t r2 = (size_t)s_idx[1 + oct + 32] * 16;

    float4 v0a = __ldg(&tab4[r0 + ol]);
    float4 v0b = __ldg(&tab4[r0 + ol + 8]);
    float4 v1a = __ldg(&tab4[r1 + ol]);
    float4 v1b = __ldg(&tab4[r1 + ol + 8]);
    float4 v2a = __ldg(&tab4[r2 + ol]);
    float4 v2b = __ldg(&tab4[r2 + ol + 8]);

    PROC(v0a, v0b, oct, true);
    PROC(v1a, v1b, oct + 16, true);
    PROC(v2a, v2b, oct + 32, true);

    // ---- Tail: conds 48 (octet 0, warp 0) and 49 (octet 8, warp 2).
    // Warp-uniform branch so shuffles see the whole warp.
    if (wid == 0 || wid == 2) {
        const bool mine = (oct == 0) || (oct == 8);
        const int c3 = 48 + (oct >> 3);                  // 48 or 49
        const size_t r3 = (size_t)(mine ? s_idx[1 + c3] : s_idx[1]) * 16;
        float4 v3a = __ldg(&tab4[r3 + ol]);
        float4 v3b = __ldg(&tab4[r3 + ol + 8]);
        PROC(v3a, v3b, c3, mine);
    }
    #undef PROC
}

extern "C" void kernel_launch(void* const* d_in, const int* in_sizes, int n_in,
                              void* d_out, int out_size)
{
    const int*   inp = (const int*)d_in[0];
    const float* tab = (const float*)d_in[1];
    float*       out = (float*)d_out;
    (void)in_sizes; (void)n_in; (void)out_size;

    cond_filter_kernel<<<BATCH, 128>>>(inp, tab, out);
}